// round 4
// baseline (speedup 1.0000x reference)
#include <cuda_runtime.h>
#include <math.h>

// Problem constants
#define NB   2
#define SS   1024
#define HH   12
#define DD   64
#define NH   (NB*HH)          // 24
#define SPLIT 16              // s-dimension splits for kernel A
#define LB    8               // l-tiles per block in kernel B
#define PV_ELEMS   (NH*DD*DD)         // 24*4096 = 98304
#define PSUM_ELEMS (NH*DD)            // 1536
#define Z_OFF      ((long long)NB*SS*HH*DD*DD)   // 100,663,296
#define Z_COUNT    (NB*SS*HH)                    // 24,576

// Deterministic scratch (no cudaMalloc allowed)
__device__ float g_pv_part[SPLIT * PV_ELEMS];     // 16 * 98304 floats
__device__ float g_psum_part[SPLIT * PSUM_ELEMS]; // 16 * 1536
__device__ float g_pv[PV_ELEMS];
__device__ float g_psum[PSUM_ELEMS];

__device__ __forceinline__ float elu1(float x) {
    return x > 0.0f ? x + 1.0f : __expf(x);
}

// ---------------------------------------------------------------------------
// Kernel A: partial pv[n,h,m,d] = sum_{s in split} p[n,s,h,d]*v[n,s,h,m]
//           partial psum[n,h,d] = sum_{s in split} p[n,s,h,d]
// grid = NH*SPLIT = 384 blocks, 256 threads.
// Thread (tm = t>>4, td = t&15) owns a 4(m) x 4(d) register tile.
// ---------------------------------------------------------------------------
__global__ __launch_bounds__(256, 4)
void kernelA(const float* __restrict__ v, const float* __restrict__ am,
             const float* __restrict__ hm, const float* __restrict__ pw) {
    int b = blockIdx.x;
    int split = b & (SPLIT - 1);
    int nh    = b >> 4;
    int n = nh / HH, h = nh % HH;
    int s0 = split * (SS / SPLIT);        // 64 rows per block

    int t  = threadIdx.x;
    int td = t & 15;      // d-quad index
    int tm = t >> 4;      // m-quad index
    int r  = t >> 4;      // load row within 16-row chunk
    int c4 = t & 15;      // load col quad

    __shared__ float4 p_s4[16][16];       // p[s][d] as float4
    __shared__ float  v_s [16][64];       // v[s][m] scalar

    float acc[4][4];
#pragma unroll
    for (int j = 0; j < 4; j++)
#pragma unroll
        for (int k = 0; k < 4; k++) acc[j][k] = 0.0f;
    float4 psum_acc = make_float4(0.f, 0.f, 0.f, 0.f);

    for (int c = 0; c < 4; c++) {
        int s = s0 + c * 16 + r;
        // load v row quad and pw row quad
        const float4 v4  = *(const float4*)(v  + (((size_t)(n*SS + s)*HH + h)*DD) + c4*4);
        const float4 pw4 = *(const float4*)(pw + (size_t)s*(HH*DD) + h*DD + c4*4);
        float msk = __ldg(am + n*SS + s);
        float4 p4;
        p4.x = elu1(pw4.x) * msk;
        p4.y = elu1(pw4.y) * msk;
        p4.z = elu1(pw4.z) * msk;
        p4.w = elu1(pw4.w) * msk;
        p_s4[r][c4] = p4;
        v_s[r][c4*4+0] = v4.x;
        v_s[r][c4*4+1] = v4.y;
        v_s[r][c4*4+2] = v4.z;
        v_s[r][c4*4+3] = v4.w;
        __syncthreads();

#pragma unroll
        for (int ss = 0; ss < 16; ss++) {
            float4 pd = p_s4[ss][td];
            if (tm == 0) {
                psum_acc.x += pd.x; psum_acc.y += pd.y;
                psum_acc.z += pd.z; psum_acc.w += pd.w;
            }
#pragma unroll
            for (int j = 0; j < 4; j++) {
                float vm = v_s[ss][tm*4 + j];
                acc[j][0] += vm * pd.x;
                acc[j][1] += vm * pd.y;
                acc[j][2] += vm * pd.z;
                acc[j][3] += vm * pd.w;
            }
        }
        __syncthreads();
    }

    float hmv = __ldg(hm + h);
    float* dst = g_pv_part + (size_t)split * PV_ELEMS + nh * (DD*DD);
#pragma unroll
    for (int j = 0; j < 4; j++) {
        float4 o;
        o.x = acc[j][0] * hmv; o.y = acc[j][1] * hmv;
        o.z = acc[j][2] * hmv; o.w = acc[j][3] * hmv;
        *(float4*)(dst + (tm*4 + j)*DD + td*4) = o;
    }
    if (tm == 0) {
        *(float4*)(g_psum_part + (size_t)split * PSUM_ELEMS + nh*DD + td*4) = psum_acc;
    }
}

// ---------------------------------------------------------------------------
// Kernel A2: reduce the SPLIT partials. Works on float4 granularity.
// pv: 24576 float4 slots; psum: 384 float4 slots.
// ---------------------------------------------------------------------------
__global__ void kernelA2() {
    int gid = blockIdx.x * 256 + threadIdx.x;
    if (gid < PV_ELEMS/4) {
        const float4* src = (const float4*)g_pv_part;
        float4 s = make_float4(0.f, 0.f, 0.f, 0.f);
#pragma unroll
        for (int k = 0; k < SPLIT; k++) {
            float4 a = src[(size_t)k * (PV_ELEMS/4) + gid];
            s.x += a.x; s.y += a.y; s.z += a.z; s.w += a.w;
        }
        ((float4*)g_pv)[gid] = s;
    } else if (gid < PV_ELEMS/4 + PSUM_ELEMS/4) {
        int i = gid - PV_ELEMS/4;
        const float4* src = (const float4*)g_psum_part;
        float4 s = make_float4(0.f, 0.f, 0.f, 0.f);
#pragma unroll
        for (int k = 0; k < SPLIT; k++) {
            float4 a = src[(size_t)k * (PSUM_ELEMS/4) + i];
            s.x += a.x; s.y += a.y; s.z += a.z; s.w += a.w;
        }
        ((float4*)g_psum)[i] = s;
    }
}

// ---------------------------------------------------------------------------
// Kernel B: stream the output.
//  ppv[n,l,h,m,d] = p[n,l,h,d] * pv[n,h,m,d]
//  z_pp[n,l,h]    = sum_d p[n,l,h,d]*psum[n,h,d] + eps
// grid = NH * (SS/LB) = 24*128 = 3072 blocks, 256 threads.
// Each block: loads one pv tile (16KB) once, emits LB=8 output tiles (128KB).
// ---------------------------------------------------------------------------
__global__ __launch_bounds__(256, 4)
void kernelB(const float* __restrict__ am, const float* __restrict__ pw,
             float* __restrict__ out, int write_z) {
    __shared__ float pv_s[DD*DD];
    __shared__ float psum_s[DD];
    __shared__ float p_s[DD];
    __shared__ float red_s[DD];

    int b  = blockIdx.x;
    int lc = b & (SS/LB - 1);     // 0..127
    int nh = b >> 7;
    int n = nh / HH, h = nh % HH;
    int t = threadIdx.x;

    float4* pv4 = (float4*)pv_s;
    const float4* gpv4 = (const float4*)g_pv + (size_t)nh * (DD*DD/4);
#pragma unroll
    for (int i = 0; i < 4; i++) pv4[t + i*256] = gpv4[t + i*256];
    if (t < DD/4) ((float4*)psum_s)[t] = ((const float4*)g_psum)[nh*(DD/4) + t];
    __syncthreads();

    for (int li = 0; li < LB; li++) {
        int l = lc * LB + li;
        if (t < DD) {
            float x   = pw[(size_t)l*(HH*DD) + h*DD + t];
            float val = elu1(x) * __ldg(am + n*SS + l);
            p_s[t]   = val;
            red_s[t] = val * psum_s[t];
        }
        __syncthreads();

        size_t base4 = ((size_t)((n*SS + l)*HH + h)) * (DD*DD/4);
        float4* o4 = (float4*)out + base4;
#pragma unroll
        for (int i = 0; i < 4; i++) {
            int idx = t + i*256;                // 0..1023 float4s; m = idx>>4, d4 = idx&15
            float4 pvv = pv4[idx];
            float4 pl  = ((float4*)p_s)[idx & 15];
            float4 r;
            r.x = pvv.x * pl.x; r.y = pvv.y * pl.y;
            r.z = pvv.z * pl.z; r.w = pvv.w * pl.w;
            __stcs(o4 + idx, r);                // streaming store: never re-read
        }
        if (write_z && t < 32) {
            float s = red_s[t] + red_s[t + 32];
#pragma unroll
            for (int off = 16; off > 0; off >>= 1)
                s += __shfl_down_sync(0xFFFFFFFFu, s, off);
            if (t == 0)
                out[Z_OFF + (size_t)(n*SS + l)*HH + h] = s + 1e-6f;
        }
        __syncthreads();
    }
}

// ---------------------------------------------------------------------------
// Launch. Inputs (metadata order): q, v, attention_mask, head_mask, pos_weight.
// q is unused by the math (only its shape matters in the reference).
// Output: ppv (N*S*H*D*D floats) followed by z_pp (N*S*H floats).
// ---------------------------------------------------------------------------
extern "C" void kernel_launch(void* const* d_in, const int* in_sizes, int n_in,
                              void* d_out, int out_size) {
    const float* v  = (const float*)d_in[1];
    const float* am = (const float*)d_in[2];
    const float* hm = (const float*)d_in[3];
    const float* pw = (const float*)d_in[4];
    float* out = (float*)d_out;

    int write_z = (long long)out_size >= Z_OFF + Z_COUNT;

    kernelA<<<NH * SPLIT, 256>>>(v, am, hm, pw);
    int totalA2 = PV_ELEMS/4 + PSUM_ELEMS/4;         // 24960
    kernelA2<<<(totalA2 + 255) / 256, 256>>>();
    kernelB<<<NH * (SS/LB), 256>>>(am, pw, out, write_z);
}

// round 5
// speedup vs baseline: 1.2045x; 1.2045x over previous
#include <cuda_runtime.h>
#include <math.h>

// Problem constants
#define NB   2
#define SS   1024
#define HH   12
#define DD   64
#define NH   (NB*HH)          // 24
#define SPLIT 32              // s-dimension splits for kernel A
#define LB    8               // l-tiles per block in kernel B
#define PV_ELEMS   (NH*DD*DD)         // 24*4096 = 98304
#define PSUM_ELEMS (NH*DD)            // 1536
#define Z_OFF      ((long long)NB*SS*HH*DD*DD)   // 100,663,296
#define Z_COUNT    (NB*SS*HH)                    // 24,576

// Deterministic scratch (no cudaMalloc allowed)
__device__ float g_pv_part[SPLIT * PV_ELEMS];     // 32 * 98304 floats
__device__ float g_psum_part[SPLIT * PSUM_ELEMS]; // 32 * 1536
__device__ float g_pv[PV_ELEMS];
__device__ float g_psum[PSUM_ELEMS];

__device__ __forceinline__ float elu1(float x) {
    return x > 0.0f ? x + 1.0f : __expf(x);
}

// ---------------------------------------------------------------------------
// Kernel A: partial pv[n,h,m,d] = sum_{s in split} p[n,s,h,d]*v[n,s,h,m]
//           partial psum[n,h,d] = sum_{s in split} p[n,s,h,d]
// grid = NH*SPLIT = 768 blocks, 256 threads, 32 s-rows per block.
// Thread (tm = t>>4, td = t&15) owns a 4(m) x 4(d) register tile.
// ---------------------------------------------------------------------------
__global__ __launch_bounds__(256, 4)
void kernelA(const float* __restrict__ v, const float* __restrict__ am,
             const float* __restrict__ hm, const float* __restrict__ pw) {
    int b = blockIdx.x;
    int split = b & (SPLIT - 1);
    int nh    = b >> 5;
    int n = nh / HH, h = nh % HH;
    int s0 = split * (SS / SPLIT);        // 32 rows per block

    int t  = threadIdx.x;
    int td = t & 15;      // d-quad index
    int tm = t >> 4;      // m-quad index
    int r  = t >> 4;      // load row within 16-row chunk
    int c4 = t & 15;      // load col quad

    __shared__ float4 p_s4[16][16];       // p[s][d] as float4
    __shared__ float  v_s [16][64];       // v[s][m] scalar

    float acc[4][4];
#pragma unroll
    for (int j = 0; j < 4; j++)
#pragma unroll
        for (int k = 0; k < 4; k++) acc[j][k] = 0.0f;
    float4 psum_acc = make_float4(0.f, 0.f, 0.f, 0.f);

    for (int c = 0; c < 2; c++) {
        int s = s0 + c * 16 + r;
        const float4 v4  = *(const float4*)(v  + (((size_t)(n*SS + s)*HH + h)*DD) + c4*4);
        const float4 pw4 = *(const float4*)(pw + (size_t)s*(HH*DD) + h*DD + c4*4);
        float msk = __ldg(am + n*SS + s);
        float4 p4;
        p4.x = elu1(pw4.x) * msk;
        p4.y = elu1(pw4.y) * msk;
        p4.z = elu1(pw4.z) * msk;
        p4.w = elu1(pw4.w) * msk;
        p_s4[r][c4] = p4;
        v_s[r][c4*4+0] = v4.x;
        v_s[r][c4*4+1] = v4.y;
        v_s[r][c4*4+2] = v4.z;
        v_s[r][c4*4+3] = v4.w;
        __syncthreads();

#pragma unroll
        for (int ss = 0; ss < 16; ss++) {
            float4 pd = p_s4[ss][td];
            if (tm == 0) {
                psum_acc.x += pd.x; psum_acc.y += pd.y;
                psum_acc.z += pd.z; psum_acc.w += pd.w;
            }
#pragma unroll
            for (int j = 0; j < 4; j++) {
                float vm = v_s[ss][tm*4 + j];
                acc[j][0] += vm * pd.x;
                acc[j][1] += vm * pd.y;
                acc[j][2] += vm * pd.z;
                acc[j][3] += vm * pd.w;
            }
        }
        __syncthreads();
    }

    float hmv = __ldg(hm + h);
    float* dst = g_pv_part + (size_t)split * PV_ELEMS + nh * (DD*DD);
#pragma unroll
    for (int j = 0; j < 4; j++) {
        float4 o;
        o.x = acc[j][0] * hmv; o.y = acc[j][1] * hmv;
        o.z = acc[j][2] * hmv; o.w = acc[j][3] * hmv;
        *(float4*)(dst + (tm*4 + j)*DD + td*4) = o;
    }
    if (tm == 0) {
        *(float4*)(g_psum_part + (size_t)split * PSUM_ELEMS + nh*DD + td*4) = psum_acc;
    }
}

// ---------------------------------------------------------------------------
// Kernel A2: reduce the SPLIT partials. Works on float4 granularity.
// ---------------------------------------------------------------------------
__global__ void kernelA2() {
    int gid = blockIdx.x * 256 + threadIdx.x;
    if (gid < PV_ELEMS/4) {
        const float4* src = (const float4*)g_pv_part;
        float4 s = make_float4(0.f, 0.f, 0.f, 0.f);
#pragma unroll
        for (int k = 0; k < SPLIT; k++) {
            float4 a = src[(size_t)k * (PV_ELEMS/4) + gid];
            s.x += a.x; s.y += a.y; s.z += a.z; s.w += a.w;
        }
        ((float4*)g_pv)[gid] = s;
    } else if (gid < PV_ELEMS/4 + PSUM_ELEMS/4) {
        int i = gid - PV_ELEMS/4;
        const float4* src = (const float4*)g_psum_part;
        float4 s = make_float4(0.f, 0.f, 0.f, 0.f);
#pragma unroll
        for (int k = 0; k < SPLIT; k++) {
            float4 a = src[(size_t)k * (PSUM_ELEMS/4) + i];
            s.x += a.x; s.y += a.y; s.z += a.z; s.w += a.w;
        }
        ((float4*)g_psum)[i] = s;
    }
}

// ---------------------------------------------------------------------------
// Kernel B: stream the output.
//  ppv[n,l,h,m,d] = p[n,l,h,d] * pv[n,h,m,d]
//  z_pp[n,l,h]    = sum_d p[n,l,h,d]*psum[n,h,d] + eps
// grid = NH * (SS/LB) = 3072 blocks, 256 threads.
// Prologue: load pv tile + psum + ALL 8 p vectors (one latency exposure),
// reduce z. Streaming loop: pure register-fed stcs stores, no barriers.
// ---------------------------------------------------------------------------
__global__ __launch_bounds__(256, 3)
void kernelB(const float* __restrict__ am, const float* __restrict__ pw,
             float* __restrict__ out, int write_z) {
    __shared__ float pv_s[DD*DD];
    __shared__ float psum_s[DD];
    __shared__ float p_all[LB*DD];     // 8 p vectors
    __shared__ float red_all[LB*DD];   // p*psum for z reduction

    int b  = blockIdx.x;
    int lc = b & (SS/LB - 1);     // 0..127
    int nh = b >> 7;
    int n = nh / HH, h = nh % HH;
    int t = threadIdx.x;

    float4* pv4 = (float4*)pv_s;
    const float4* gpv4 = (const float4*)g_pv + (size_t)nh * (DD*DD/4);
#pragma unroll
    for (int i = 0; i < 4; i++) pv4[t + i*256] = gpv4[t + i*256];
    if (t < DD/4) ((float4*)psum_s)[t] = ((const float4*)g_psum)[nh*(DD/4) + t];
    __syncthreads();

    // All LB p vectors in one shot: 512 elements, 2 per thread
#pragma unroll
    for (int i = 0; i < 2; i++) {
        int idx = t + i*256;
        int li  = idx >> 6;
        int d   = idx & 63;
        int l   = lc * LB + li;
        float x   = pw[(size_t)l*(HH*DD) + h*DD + d];
        float val = elu1(x) * __ldg(am + n*SS + l);
        p_all[idx]   = val;
        red_all[idx] = val * psum_s[d];
    }
    __syncthreads();

    // z_pp: warp w reduces l-tile w
    if (write_z) {
        int w = t >> 5, lane = t & 31;
        float s = red_all[w*64 + lane] + red_all[w*64 + 32 + lane];
#pragma unroll
        for (int off = 16; off > 0; off >>= 1)
            s += __shfl_down_sync(0xFFFFFFFFu, s, off);
        if (lane == 0)
            out[Z_OFF + (size_t)(n*SS + lc*LB + w)*HH + h] = s + 1e-6f;
    }

    // Register-resident operands: pl depends only on li (idx&15 == t&15),
    // pvv depends only on i. 32 independent streaming stores per thread.
    float4 pl[LB];
#pragma unroll
    for (int li = 0; li < LB; li++)
        pl[li] = ((float4*)p_all)[li*16 + (t & 15)];
    float4 pvv[4];
#pragma unroll
    for (int i = 0; i < 4; i++)
        pvv[i] = pv4[t + i*256];

#pragma unroll
    for (int li = 0; li < LB; li++) {
        size_t base4 = ((size_t)((n*SS + lc*LB + li)*HH + h)) * (DD*DD/4);
        float4* o4 = (float4*)out + base4;
#pragma unroll
        for (int i = 0; i < 4; i++) {
            float4 r;
            r.x = pvv[i].x * pl[li].x;
            r.y = pvv[i].y * pl[li].y;
            r.z = pvv[i].z * pl[li].z;
            r.w = pvv[i].w * pl[li].w;
            __stcs(o4 + t + i*256, r);
        }
    }
}

// ---------------------------------------------------------------------------
// Launch. Inputs (metadata order): q, v, attention_mask, head_mask, pos_weight.
// q is unused by the math (only its shape matters in the reference).
// Output: ppv (N*S*H*D*D floats) followed by z_pp (N*S*H floats).
// ---------------------------------------------------------------------------
extern "C" void kernel_launch(void* const* d_in, const int* in_sizes, int n_in,
                              void* d_out, int out_size) {
    const float* v  = (const float*)d_in[1];
    const float* am = (const float*)d_in[2];
    const float* hm = (const float*)d_in[3];
    const float* pw = (const float*)d_in[4];
    float* out = (float*)d_out;

    int write_z = (long long)out_size >= Z_OFF + Z_COUNT;

    kernelA<<<NH * SPLIT, 256>>>(v, am, hm, pw);
    int totalA2 = PV_ELEMS/4 + PSUM_ELEMS/4;         // 24960
    kernelA2<<<(totalA2 + 255) / 256, 256>>>();
    kernelB<<<NH * (SS/LB), 256>>>(am, pw, out, write_z);
}